// round 13
// baseline (speedup 1.0000x reference)
#include <cuda_runtime.h>
#include <cstdint>
#include <cstring>

// Correlation: out[b,d,h,w] = (1/256) * sum_c in1[b,c,h,w] * in2[b,c,h+dy,w+dx]
//   B=16, C=256, H=48, W=64; dy,dx in {-20,...,20} step 2 (21 each), zero padded.
//
// Grid (48, 16, 2): CTA per (h, b, jy-group). Group 0: jy 0..10, group 1: jy 11..20.
// 176 threads: tid -> r=tid&15 (uoct=r>>1 -> W0=8*uoct, half=r&1), jyl=tid>>4.
// Thread computes 8 w x 11 jx via packed fma.rn.f32x2 (44 b64 accumulators).
// Channels stream in CC=4 chunks through TRIPLE-buffered dynamic smem via
// cp.async with ONE __syncthreads per iteration (WAR pushed out one stage).
// Fill descriptors precomputed once (<=5/thread); pad regions zeroed once.

#define NB 16
#define NC 256
#define NH 48
#define NW 64
#define ND 21
#define NDISP 441
#define WINP 104
#define CC 4
#define NK (NC / CC)
#define NTHREADS 176
#define NROWS 11
#define HW (NH * NW)
#define SD 5                      // descriptor slots per thread
#define NSTAGE 3

#define CCF (64 + NROWS * WINP)   // 1208 floats per cc block
#define BUFF (CC * CCF)           // 4832 floats per buffer
#define BUFBYTES (BUFF * 4)       // 19328 B
#define SMEM_TOTAL (NSTAGE * BUFBYTES)   // 57984 B (dynamic)
#define SRCSTRIDE (CC * HW * 4)   // global src advance per chunk (bytes)

static_assert((CCF * 4) % 16 == 0, "cc block must stay 16B aligned");
static_assert(SD * NTHREADS >= CC * 16 * (1 + NROWS + 1), "descriptor slots");

__device__ __forceinline__ unsigned smem_u32(const void* p) {
    return (unsigned)__cvta_generic_to_shared(p);
}
__device__ __forceinline__ void cp16(unsigned sdst, const void* gsrc) {
    asm volatile("cp.async.cg.shared.global [%0], [%1], 16;\n" :: "r"(sdst), "l"(gsrc));
}
__device__ __forceinline__ void fma2(unsigned long long& d,
                                     unsigned long long a,
                                     unsigned long long b) {
    asm("fma.rn.f32x2 %0, %1, %2, %3;" : "=l"(d) : "l"(a), "l"(b), "l"(d));
}

extern __shared__ float sm_dyn[];

__global__ __launch_bounds__(NTHREADS, 2)
void corr_kernel(const float* __restrict__ in1,
                 const float* __restrict__ in2,
                 float* __restrict__ out) {
    const int h    = blockIdx.x;
    const int b    = blockIdx.y;
    const int g    = blockIdx.z;        // jy group
    const int jylo = g ? 11 : 0;
    const int njy  = g ? 10 : 11;
    const int tid  = threadIdx.x;
    const int r    = tid & 15;
    const int jyl  = tid >> 4;          // local jy index, valid < njy
    const int uoct = r >> 1;
    const int half = r & 1;
    const int W0   = uoct * 8;
    const int wb   = W0 + (half ? 20 : 0);  // window float base (16B aligned)
    const bool active = (jyl < njy);

    // ---- zero all stages once (pad regions stay zero forever) ----
    {
        float4 z = make_float4(0.f, 0.f, 0.f, 0.f);
        float4* p = (float4*)&sm_dyn[0];
        const int n4 = NSTAGE * BUFF / 4;
        for (int idx = tid; idx < n4; idx += NTHREADS) p[idx] = z;
    }

    // ---- precompute fill descriptors (valid 16B chunks only) ----
    const int row_lo_g = max(0, (21 - h) >> 1);      // global valid dy rows
    const int row_hi_g = min(20, (67 - h) >> 1);
    const int rlo = max(row_lo_g, jylo);
    const int rhi = min(row_hi_g, jylo + njy - 1);
    const int nv  = (rhi >= rlo) ? (rhi - rlo + 1) : 0;
    const int per   = 16 * (1 + nv);    // items per cc
    const int total = CC * per;         // <= 4*16*12 = 768 <= SD*NTHREADS

    unsigned dstoff[SD];
    const char* srcp[SD];
    bool val[SD];
    #pragma unroll
    for (int s = 0; s < SD; ++s) {
        const int i = tid + s * NTHREADS;
        val[s] = (i < total);
        dstoff[s] = 0; srcp[s] = (const char*)in1;
        if (val[s]) {
            const int cc  = i / per;
            const int rem = i - cc * per;
            if (rem < 16) {
                dstoff[s] = (cc * CCF + rem * 4) * 4;
                srcp[s] = (const char*)(in1 + (((size_t)b * NC + cc) * NH + h) * NW + rem * 4);
            } else {
                const int rr  = rem - 16;
                const int v   = rr >> 4;
                const int q   = (rr & 15) + 5;       // 16B chunk in [5,21) of window
                const int row = rlo + v;             // global dy row
                const int gr  = h + 2 * row - 20;    // in-bounds by construction
                dstoff[s] = (cc * CCF + 64 + (row - jylo) * WINP + q * 4) * 4;
                srcp[s] = (const char*)(in2 + (((size_t)b * NC + cc) * NH + gr) * NW + (q * 4 - 20));
            }
        }
    }

    const unsigned sbase = smem_u32(&sm_dyn[0]);

    __syncthreads();   // zeros visible before any cp.async lands

    // prologue: fill chunks 0 and 1 into stages 0 and 1
    #pragma unroll
    for (int s = 0; s < SD; ++s)
        if (val[s]) { cp16(sbase + dstoff[s], srcp[s]); srcp[s] += SRCSTRIDE; }
    asm volatile("cp.async.commit_group;\n");
    #pragma unroll
    for (int s = 0; s < SD; ++s)
        if (val[s]) { cp16(sbase + BUFBYTES + dstoff[s], srcp[s]); srcp[s] += SRCSTRIDE; }
    asm volatile("cp.async.commit_group;\n");
    asm volatile("cp.async.wait_group 1;\n");   // chunk 0 resident
    __syncthreads();                            // chunk 0 visible CTA-wide

    unsigned long long acc2[11][4];
    #pragma unroll
    for (int j = 0; j < 11; ++j)
        #pragma unroll
        for (int p = 0; p < 4; ++p) acc2[j][p] = 0ull;

    int stage_fill = 2;   // stage receiving chunk k+2
    int stage_cur  = 0;   // stage holding chunk k

    for (int k = 0; k < NK; ++k) {
        if (k + 2 < NK) {
            const unsigned boff = stage_fill * BUFBYTES;
            #pragma unroll
            for (int s = 0; s < SD; ++s)
                if (val[s]) { cp16(sbase + boff + dstoff[s], srcp[s]); srcp[s] += SRCSTRIDE; }
        }
        asm volatile("cp.async.commit_group;\n");
        asm volatile("cp.async.wait_group 1;\n");   // chunks <= k+1 done (this thread)

        if (active) {
            const float* B = &sm_dyn[stage_cur * BUFF];
            #pragma unroll
            for (int cc = 0; cc < CC; ++cc) {
                const float* s1r = B + cc * CCF;
                const float* s2r = B + cc * CCF + 64 + jyl * WINP;
                unsigned long long a2[4];
                {
                    ulonglong2 t0 = *(const ulonglong2*)&s1r[W0];
                    ulonglong2 t1 = *(const ulonglong2*)&s1r[W0 + 4];
                    a2[0] = t0.x; a2[1] = t0.y; a2[2] = t1.x; a2[3] = t1.y;
                }
                unsigned long long f2[14];
                #pragma unroll
                for (int t = 0; t < 7; ++t) {
                    ulonglong2 v = *(const ulonglong2*)&s2r[wb + 4 * t];
                    f2[2 * t] = v.x; f2[2 * t + 1] = v.y;
                }
                // acc2[j][p] covers out w = W0+2p..2p+1, jx = half*10 + j.
                #pragma unroll
                for (int j = 0; j < 11; ++j)
                    #pragma unroll
                    for (int p = 0; p < 4; ++p)
                        fma2(acc2[j][p], a2[p], f2[j + p]);
            }
        }
        __syncthreads();   // compute(k) done CTA-wide; chunk k+1 visible next iter

        stage_cur  = (stage_cur  + 1 == NSTAGE) ? 0 : stage_cur + 1;
        stage_fill = (stage_fill + 1 == NSTAGE) ? 0 : stage_fill + 1;
    }

    if (active) {
        const float inv = 1.0f / 256.0f;
        const int jy = jylo + jyl;
        #pragma unroll
        for (int j = 0; j < 11; ++j) {
            if (j >= half) {                  // half=1: j=0 duplicates jx=10
                const int jx = half * 10 + j;
                float* o = out + ((((size_t)b * NDISP + (size_t)jy * ND + jx) * NH + h) * NW) + W0;
                float2 u[4];
                #pragma unroll
                for (int p = 0; p < 4; ++p)
                    memcpy(&u[p], &acc2[j][p], 8);
                float4 v0, v1;
                v0.x = u[0].x * inv; v0.y = u[0].y * inv;
                v0.z = u[1].x * inv; v0.w = u[1].y * inv;
                v1.x = u[2].x * inv; v1.y = u[2].y * inv;
                v1.z = u[3].x * inv; v1.w = u[3].y * inv;
                *(float4*)o = v0;
                *(float4*)(o + 4) = v1;
            }
        }
    }
}

extern "C" void kernel_launch(void* const* d_in, const int* in_sizes, int n_in,
                              void* d_out, int out_size) {
    const float* in1 = (const float*)d_in[0];
    const float* in2 = (const float*)d_in[1];
    float* out = (float*)d_out;
    cudaFuncSetAttribute(corr_kernel,
                         cudaFuncAttributeMaxDynamicSharedMemorySize, SMEM_TOTAL);
    dim3 grid(NH, NB, 2);
    corr_kernel<<<grid, NTHREADS, SMEM_TOTAL>>>(in1, in2, out);
}